// round 1
// baseline (speedup 1.0000x reference)
#include <cuda_runtime.h>
#include <cuda_bf16.h>

// Bilinear grid sampler: B=16, H=256, W=256, C=64, fp32.
// Layout: U [B,H,W,C], grid [B,H,W,2], out [B,H,W,C].
// Strategy: 16 threads per output pixel, one float4 (16B = 4 channels) per
// thread -> each corner gather is a coalesced 256B segment per half-warp.

#define BS_B 16
#define BS_H 256
#define BS_W 256
#define BS_C 64
#define BS_PIX (BS_B * BS_H * BS_W)          // 1,048,576 pixels
#define LANES_PER_PIX 16                      // 16 * float4 = 64 channels

__global__ __launch_bounds__(256)
void bilinear_sampler_kernel(const float* __restrict__ U,
                             const float* __restrict__ grid,
                             float* __restrict__ out)
{
    const long long tid = (long long)blockIdx.x * blockDim.x + threadIdx.x;
    const int pix  = (int)(tid >> 4);         // pixel index
    const int lane = (int)(tid & 15);         // float4 slot within channel dim
    if (pix >= BS_PIX) return;

    // Decompose pixel index: pix = ((b*H + h)*W + w)
    const int b  = pix >> 16;                 // / (256*256)
    // (h, w not needed separately; only b for base, but grid is indexed by pix)

    // Load grid coords (all 16 lanes of a pixel read the same 8 bytes; L1 broadcast)
    const float2 g = __ldg((const float2*)(grid) + pix);

    // Denormalize: x in [0, W-1], y in [0, H-1]
    const float x = 0.5f * (g.x + 1.0f) * (float)(BS_W - 1);
    const float y = 0.5f * (g.y + 1.0f) * (float)(BS_H - 1);

    const int x0 = (int)floorf(x);
    const int y0 = (int)floorf(y);
    const int x1 = x0 + 1;
    const int y1 = y0 + 1;

    const int x0c = min(max(x0, 0), BS_W - 1);
    const int x1c = min(max(x1, 0), BS_W - 1);
    const int y0c = min(max(y0, 0), BS_H - 1);
    const int y1c = min(max(y1, 0), BS_H - 1);

    const float x0f = (float)x0c, x1f = (float)x1c;
    const float y0f = (float)y0c, y1f = (float)y1c;

    const float wa = (x1f - x) * (y1f - y);
    const float wb = (x1f - x) * (y - y0f);
    const float wc = (x - x0f) * (y1f - y);
    const float wd = (x - x0f) * (y - y0f);

    // U viewed as float4: [B,H,W, C/4=16]
    const float4* __restrict__ U4 = (const float4*)U;
    const long long base = (long long)b * (BS_H * BS_W);
    const long long ia = ((base + (long long)y0c * BS_W + x0c) << 4) + lane;
    const long long ib = ((base + (long long)y1c * BS_W + x0c) << 4) + lane;
    const long long ic = ((base + (long long)y0c * BS_W + x1c) << 4) + lane;
    const long long id = ((base + (long long)y1c * BS_W + x1c) << 4) + lane;

    const float4 Ia = __ldg(U4 + ia);
    const float4 Ib = __ldg(U4 + ib);
    const float4 Ic = __ldg(U4 + ic);
    const float4 Id = __ldg(U4 + id);

    float4 r;
    r.x = wa * Ia.x + wb * Ib.x + wc * Ic.x + wd * Id.x;
    r.y = wa * Ia.y + wb * Ib.y + wc * Ic.y + wd * Id.y;
    r.z = wa * Ia.z + wb * Ib.z + wc * Ic.z + wd * Id.z;
    r.w = wa * Ia.w + wb * Ib.w + wc * Ic.w + wd * Id.w;

    ((float4*)out)[((long long)pix << 4) + lane] = r;
}

extern "C" void kernel_launch(void* const* d_in, const int* in_sizes, int n_in,
                              void* d_out, int out_size)
{
    const float* U    = (const float*)d_in[0];
    const float* grid = (const float*)d_in[1];
    float* out        = (float*)d_out;

    const long long total_threads = (long long)BS_PIX * LANES_PER_PIX; // 16.7M
    const int block = 256;
    const int gridsz = (int)((total_threads + block - 1) / block);     // 65536
    bilinear_sampler_kernel<<<gridsz, block>>>(U, grid, out);
}

// round 2
// speedup vs baseline: 1.1441x; 1.1441x over previous
#include <cuda_runtime.h>
#include <cuda_bf16.h>

// Bilinear grid sampler: B=16, H=256, W=256, C=64, fp32.
// U [B,H,W,C], grid [B,H,W,2], out [B,H,W,C].
// 16 threads per pixel, one float4 per thread (coalesced 256B per corner).
// Each thread processes TWO pixels (g and g + PIX/2) -> 8 independent
// front-batched LDG.128 per thread for DRAM latency hiding (MLP=8).
// All indices are 32-bit (max float4 index = 16.7M < 2^31).

#define BS_B 16
#define BS_H 256
#define BS_W 256
#define BS_PIX (BS_B * BS_H * BS_W)     // 1,048,576
#define HALF_PIX (BS_PIX / 2)           // 524,288

__device__ __forceinline__ void pixel_setup(const float2 g,
                                            int b, int lane,
                                            int& ia, int& ib, int& ic, int& id,
                                            float& wa, float& wb, float& wc, float& wd)
{
    const float x = 0.5f * (g.x + 1.0f) * (float)(BS_W - 1);
    const float y = 0.5f * (g.y + 1.0f) * (float)(BS_H - 1);

    const int x0 = (int)floorf(x);
    const int y0 = (int)floorf(y);

    const int x0c = min(max(x0, 0), BS_W - 1);
    const int x1c = min(max(x0 + 1, 0), BS_W - 1);
    const int y0c = min(max(y0, 0), BS_H - 1);
    const int y1c = min(max(y0 + 1, 0), BS_H - 1);

    const float x0f = (float)x0c, x1f = (float)x1c;
    const float y0f = (float)y0c, y1f = (float)y1c;

    wa = (x1f - x) * (y1f - y);
    wb = (x1f - x) * (y - y0f);
    wc = (x - x0f) * (y1f - y);
    wd = (x - x0f) * (y - y0f);

    // float4 index space: [B, H, W, 16]
    const int base = b << 16;                       // b * H * W
    const int r0 = (base + (y0c << 8)) << 4;        // (b*HW + y0*W) * 16
    const int r1 = (base + (y1c << 8)) << 4;
    const int xo0 = (x0c << 4) + lane;
    const int xo1 = (x1c << 4) + lane;
    ia = r0 + xo0;
    ib = r1 + xo0;
    ic = r0 + xo1;
    id = r1 + xo1;
}

__global__ __launch_bounds__(256)
void bilinear_sampler_kernel(const float* __restrict__ U,
                             const float* __restrict__ grid,
                             float* __restrict__ out)
{
    const int t    = blockIdx.x * 256 + threadIdx.x;
    const int lane = t & 15;
    const int g    = t >> 4;                 // 0 .. HALF_PIX-1
    const int pix0 = g;
    const int pix1 = g + HALF_PIX;

    const float2* __restrict__ grid2 = (const float2*)grid;
    const float2 g0 = __ldg(grid2 + pix0);
    const float2 g1 = __ldg(grid2 + pix1);

    int ia0, ib0, ic0, id0, ia1, ib1, ic1, id1;
    float wa0, wb0, wc0, wd0, wa1, wb1, wc1, wd1;
    pixel_setup(g0, pix0 >> 16, lane, ia0, ib0, ic0, id0, wa0, wb0, wc0, wd0);
    pixel_setup(g1, pix1 >> 16, lane, ia1, ib1, ic1, id1, wa1, wb1, wc1, wd1);

    const float4* __restrict__ U4 = (const float4*)U;

    // 8 independent loads, front-batched for MLP=8
    const float4 A0 = __ldg(U4 + ia0);
    const float4 B0 = __ldg(U4 + ib0);
    const float4 C0 = __ldg(U4 + ic0);
    const float4 D0 = __ldg(U4 + id0);
    const float4 A1 = __ldg(U4 + ia1);
    const float4 B1 = __ldg(U4 + ib1);
    const float4 C1 = __ldg(U4 + ic1);
    const float4 D1 = __ldg(U4 + id1);

    float4 r0, r1;
    r0.x = wa0 * A0.x + wb0 * B0.x + wc0 * C0.x + wd0 * D0.x;
    r0.y = wa0 * A0.y + wb0 * B0.y + wc0 * C0.y + wd0 * D0.y;
    r0.z = wa0 * A0.z + wb0 * B0.z + wc0 * C0.z + wd0 * D0.z;
    r0.w = wa0 * A0.w + wb0 * B0.w + wc0 * C0.w + wd0 * D0.w;

    r1.x = wa1 * A1.x + wb1 * B1.x + wc1 * C1.x + wd1 * D1.x;
    r1.y = wa1 * A1.y + wb1 * B1.y + wc1 * C1.y + wd1 * D1.y;
    r1.z = wa1 * A1.z + wb1 * B1.z + wc1 * C1.z + wd1 * D1.z;
    r1.w = wa1 * A1.w + wb1 * B1.w + wc1 * C1.w + wd1 * D1.w;

    float4* __restrict__ out4 = (float4*)out;
    out4[(pix0 << 4) + lane] = r0;
    out4[(pix1 << 4) + lane] = r1;
}

extern "C" void kernel_launch(void* const* d_in, const int* in_sizes, int n_in,
                              void* d_out, int out_size)
{
    const float* U    = (const float*)d_in[0];
    const float* grid = (const float*)d_in[1];
    float* out        = (float*)d_out;

    // HALF_PIX pixel-pairs * 16 lanes = 8,388,608 threads
    const int block = 256;
    const int gridsz = (HALF_PIX * 16) / block;   // 32768
    bilinear_sampler_kernel<<<gridsz, block>>>(U, grid, out);
}